// round 2
// baseline (speedup 1.0000x reference)
#include <cuda_runtime.h>
#include <math.h>

// ---- problem constants ----
#define SQ    1024      // sequence length
#define HDIM  1024      // hidden size
#define NHQ   16        // query heads
#define NKV   8         // kv heads
#define HD    64        // head dim
#define NE    64        // experts
#define TOPK  8
#define CAP   512       // capacity
#define IS    3072      // intermediate
#define QKVN  2048      // (16+2*8)*64

// ---- scratch (device globals; allocation-free) ----
__device__ float g_xln[SQ*HDIM];
__device__ float g_qkv[SQ*QKVN];
__device__ float g_q[NHQ*SQ*HD];
__device__ float g_k[NKV*SQ*HD];
__device__ float g_v[NKV*SQ*HD];
__device__ float g_sc[(size_t)NHQ*SQ*SQ];          // 67 MB
__device__ float g_attnT[SQ*HDIM];
__device__ float g_tmp[SQ*HDIM];
__device__ float g_h1[SQ*HDIM];
__device__ float g_x2[SQ*HDIM];
__device__ float g_gu[SQ*2*IS];
__device__ float g_act[SQ*IS];
__device__ float g_mlp[SQ*HDIM];
__device__ float g_logits[SQ*NE];
__device__ int   g_eidx[SQ*TOPK];
__device__ float g_ew[SQ*TOPK];
__device__ int   g_epos[SQ*TOPK];
__device__ int   g_cnt[NE];
__device__ float g_xe[(size_t)NE*CAP*HDIM];        // 128 MB
__device__ float g_gue[(size_t)NE*CAP*2*IS];       // 805 MB
__device__ float g_acte[(size_t)NE*CAP*IS];        // 402 MB
__device__ float g_ye[(size_t)NE*CAP*HDIM];        // 128 MB

// ============================================================
// Generic tiled SGEMM: C = alpha * A(MxK) * B(KxN)  (TB=0)
//                      C = alpha * A(MxK) * B(NxK)^T (TB=1)
// 64x64 tile, 16 k-slice, 256 threads, 4x4 microtile.
// Batched over blockIdx.z with per-operand strides; B batch index = z/bdiv.
// Optional per-batch row count (mcnt) for expert-capacity early exit.
// Requires M%64==0, N%64==0, K%16==0 (true for all call sites).
// ============================================================
template<int TB>
__global__ void __launch_bounds__(256) sgemm_t(
    const float* __restrict__ A, const float* __restrict__ B,
    float* __restrict__ C, int M, int N, int K,
    int lda, int ldb, int ldc, float alpha,
    long sA, long sB, long sC, int bdiv, const int* mcnt)
{
    int z = blockIdx.z;
    A += (long)z * sA;
    B += (long)(z / bdiv) * sB;
    C += (long)z * sC;
    int m0 = blockIdx.y * 64;
    int n0 = blockIdx.x * 64;
    if (mcnt) {
        int me = mcnt[z]; if (me > M) me = M;
        if (m0 >= me) return;
    }
    __shared__ float As[16][64];
    __shared__ float Bs[16][64];
    const int tid = threadIdx.x;
    const int tx = tid & 15, ty = tid >> 4;
    const int am = tid >> 2, ak = (tid & 3) << 2;   // transposed loader
    const int bn = (tid & 15) << 2, bk = tid >> 4;  // row loader
    float acc[4][4] = {};
    for (int k0 = 0; k0 < K; k0 += 16) {
        float4 av = *(const float4*)(A + (long)(m0 + am) * lda + (k0 + ak));
        As[ak+0][am] = av.x; As[ak+1][am] = av.y;
        As[ak+2][am] = av.z; As[ak+3][am] = av.w;
        if (TB == 0) {
            float4 bv = *(const float4*)(B + (long)(k0 + bk) * ldb + (n0 + bn));
            *(float4*)(&Bs[bk][bn]) = bv;
        } else {
            float4 bv = *(const float4*)(B + (long)(n0 + am) * ldb + (k0 + ak));
            Bs[ak+0][am] = bv.x; Bs[ak+1][am] = bv.y;
            Bs[ak+2][am] = bv.z; Bs[ak+3][am] = bv.w;
        }
        __syncthreads();
        #pragma unroll
        for (int kk = 0; kk < 16; kk++) {
            float a0 = As[kk][ty*4+0], a1 = As[kk][ty*4+1];
            float a2 = As[kk][ty*4+2], a3 = As[kk][ty*4+3];
            float b0 = Bs[kk][tx*4+0], b1 = Bs[kk][tx*4+1];
            float b2 = Bs[kk][tx*4+2], b3 = Bs[kk][tx*4+3];
            acc[0][0] += a0*b0; acc[0][1] += a0*b1; acc[0][2] += a0*b2; acc[0][3] += a0*b3;
            acc[1][0] += a1*b0; acc[1][1] += a1*b1; acc[1][2] += a1*b2; acc[1][3] += a1*b3;
            acc[2][0] += a2*b0; acc[2][1] += a2*b1; acc[2][2] += a2*b2; acc[2][3] += a2*b3;
            acc[3][0] += a3*b0; acc[3][1] += a3*b1; acc[3][2] += a3*b2; acc[3][3] += a3*b3;
        }
        __syncthreads();
    }
    float* Cp = C + (long)(m0 + ty*4) * ldc + n0 + tx*4;
    #pragma unroll
    for (int i = 0; i < 4; i++) {
        #pragma unroll
        for (int j = 0; j < 4; j++) Cp[j] = alpha * acc[i][j];
        Cp += ldc;
    }
}

// ---------- small kernels ----------
__global__ void zero_cnt_k() { if (threadIdx.x < NE) g_cnt[threadIdx.x] = 0; }

__global__ void rmsnorm_k(const float* __restrict__ x, const float* __restrict__ w,
                          float* __restrict__ y, int ncols)
{
    int row = blockIdx.x;
    const float* xr = x + (long)row * ncols;
    float ss = 0.f;
    for (int i = threadIdx.x; i < ncols; i += 256) { float v = xr[i]; ss += v * v; }
    __shared__ float red[256];
    red[threadIdx.x] = ss; __syncthreads();
    for (int s = 128; s > 0; s >>= 1) {
        if (threadIdx.x < s) red[threadIdx.x] += red[threadIdx.x + s];
        __syncthreads();
    }
    float inv = rsqrtf(red[0] / (float)ncols + 1e-6f);
    for (int i = threadIdx.x; i < ncols; i += 256)
        y[(long)row * ncols + i] = w[i] * xr[i] * inv;
}

// RoPE + per-head RMSNorm + split/copy into q/k/v layouts. grid (SQ, 32), 64 thr.
__global__ void rope_split_k(const float* __restrict__ cosb, const float* __restrict__ sinb,
                             const float* __restrict__ qw, const float* __restrict__ knw)
{
    int s = blockIdx.x;
    int hh = blockIdx.y;     // 0..15 q heads, 16..23 k heads, 24..31 v heads
    int d = threadIdx.x;     // 0..63
    if (hh >= 24) {
        int kvh = hh - 24;
        int col = kvh * 256 + 192 + d;
        g_v[((long)kvh * SQ + s) * HD + d] = g_qkv[(long)s * QKVN + col];
        return;
    }
    __shared__ float buf[64];
    __shared__ float red2[2];
    int col; float* dst; const float* w;
    if (hh < 16) {
        int kvh = hh >> 1, slot = hh & 1;
        col = kvh * 256 + slot * 64 + d;
        dst = g_q + ((long)hh * SQ + s) * HD;
        w = qw;
    } else {
        int kvh = hh - 16;
        col = kvh * 256 + 128 + d;
        dst = g_k + ((long)kvh * SQ + s) * HD;
        w = knw;
    }
    float v = g_qkv[(long)s * QKVN + col];
    buf[d] = v;
    __syncthreads();
    float rh = (d < 32) ? -buf[d + 32] : buf[d - 32];
    float r = v * cosb[s * HD + d] + rh * sinb[s * HD + d];
    float ss = r * r;
    for (int off = 16; off > 0; off >>= 1) ss += __shfl_xor_sync(0xffffffffu, ss, off);
    if ((d & 31) == 0) red2[d >> 5] = ss;
    __syncthreads();
    float tot = red2[0] + red2[1];
    dst[d] = w[d] * r * rsqrtf(tot / 64.f + 1e-6f);
}

// causal softmax per (h, q) row; zero masked entries. grid (SQ, NHQ), 256 thr.
__global__ void softmax_causal_k()
{
    int q = blockIdx.x, h = blockIdx.y, t = threadIdx.x;
    float* row = g_sc + ((size_t)h * SQ + q) * SQ;
    __shared__ float red[256];
    float m = -1e30f;
    for (int k = t; k <= q; k += 256) m = fmaxf(m, row[k]);
    red[t] = m; __syncthreads();
    for (int s = 128; s > 0; s >>= 1) { if (t < s) red[t] = fmaxf(red[t], red[t + s]); __syncthreads(); }
    m = red[0]; __syncthreads();
    float ssum = 0.f;
    for (int k = t; k <= q; k += 256) { float e = expf(row[k] - m); row[k] = e; ssum += e; }
    red[t] = ssum; __syncthreads();
    for (int s = 128; s > 0; s >>= 1) { if (t < s) red[t] += red[t + s]; __syncthreads(); }
    float inv = 1.f / red[0];
    for (int k = t; k <= q; k += 256) row[k] *= inv;
    for (int k = q + 1 + t; k < SQ; k += 256) row[k] = 0.f;
}

__global__ void add_k(const float* __restrict__ a, const float* __restrict__ b,
                      float* __restrict__ c, int n)
{
    int i = blockIdx.x * 256 + threadIdx.x;
    if (i < n) c[i] = a[i] + b[i];
}

// shared-MLP SwiGLU: act = gu[:, :I] * silu(gu[:, I:])
__global__ void swiglu_shared_k()
{
    long t = blockIdx.x;
    const float* g = g_gu + t * (2 * IS);
    float* a = g_act + t * IS;
    for (int i = threadIdx.x; i < IS; i += 256) {
        float x1 = g[i], xb = g[IS + i];
        a[i] = x1 * (xb / (1.f + expf(-xb)));
    }
}

// gate softmax + top-8 + normalize (one thread per token)
__global__ void route_k()
{
    int t = blockIdx.x * 256 + threadIdx.x;
    if (t >= SQ) return;
    float l[NE];
    float m = -1e30f;
    for (int e = 0; e < NE; e++) { l[e] = g_logits[t * NE + e]; m = fmaxf(m, l[e]); }
    float sum = 0.f;
    for (int e = 0; e < NE; e++) { l[e] = expf(l[e] - m); sum += l[e]; }
    float inv = 1.f / sum;
    for (int e = 0; e < NE; e++) l[e] *= inv;
    int chosen[TOPK]; float wv[TOPK]; float wsum = 0.f;
    for (int k = 0; k < TOPK; k++) {
        float best = -1.f; int bi = 0;
        for (int e = 0; e < NE; e++) if (l[e] > best) { best = l[e]; bi = e; }
        chosen[k] = bi; wv[k] = best; l[bi] = -2.f; wsum += best;
    }
    float dn = fmaxf(wsum, 1.1920929e-07f);
    for (int k = 0; k < TOPK; k++) {
        g_eidx[t * TOPK + k] = chosen[k];
        g_ew[t * TOPK + k] = wv[k] / dn;
    }
}

// deterministic in-order position assignment (matches jax cumsum(one_hot)).
// one block per expert; scans all 8192 slots in flattened (t,k) order.
__global__ void assign_pos_k()
{
    int e = blockIdx.x;
    int t = threadIdx.x;                 // 256 threads, 32 slots each
    const int CH = (SQ * TOPK) / 256;    // 32
    __shared__ int sc[256];
    __shared__ int off[256];
    int c = 0;
    int base = t * CH;
    for (int i = 0; i < CH; i++) c += (g_eidx[base + i] == e);
    sc[t] = c; __syncthreads();
    if (t == 0) {
        int r = 0;
        for (int i = 0; i < 256; i++) { off[i] = r; r += sc[i]; }
        g_cnt[e] = r;
    }
    __syncthreads();
    int p = off[t];
    for (int i = 0; i < CH; i++) {
        int s = base + i;
        if (g_eidx[s] == e) g_epos[s] = p++;
    }
}

// scatter tokens into expert capacity buffer
__global__ void scatter_xe_k()
{
    int slot = blockIdx.x;            // t*8+k
    int p = g_epos[slot];
    if (p >= CAP) return;
    int e = g_eidx[slot];
    int t = slot >> 3;
    const float* src = g_x2 + (long)t * HDIM;
    float* dst = g_xe + ((size_t)e * CAP + p) * HDIM;
    for (int i = threadIdx.x; i < HDIM; i += 256) dst[i] = src[i];
}

// expert SwiGLU (only occupied rows)
__global__ void swiglu_expert_k()
{
    int row = blockIdx.x;             // 0..NE*CAP-1
    int e = row >> 9, r = row & 511;
    int me = g_cnt[e]; if (me > CAP) me = CAP;
    if (r >= me) return;
    const float* g = g_gue + (size_t)row * (2 * IS);
    float* a = g_acte + (size_t)row * IS;
    for (int i = threadIdx.x; i < IS; i += 256) {
        float x1 = g[i], xb = g[IS + i];
        a[i] = x1 * (xb / (1.f + expf(-xb)));
    }
}

// out = h1 + shared_mlp + sum_k w_k * ye[e_k][p_k]
__global__ void combine_k(float* __restrict__ out)
{
    int t = blockIdx.x;
    __shared__ int es[TOPK]; __shared__ int ps[TOPK]; __shared__ float ws[TOPK];
    if (threadIdx.x < TOPK) {
        es[threadIdx.x] = g_eidx[t * TOPK + threadIdx.x];
        ps[threadIdx.x] = g_epos[t * TOPK + threadIdx.x];
        ws[threadIdx.x] = g_ew[t * TOPK + threadIdx.x];
    }
    __syncthreads();
    for (int i = threadIdx.x; i < HDIM; i += 256) {
        float v = g_h1[(long)t * HDIM + i] + g_mlp[(long)t * HDIM + i];
        #pragma unroll
        for (int k = 0; k < TOPK; k++) {
            if (ps[k] < CAP)
                v += ws[k] * g_ye[((size_t)es[k] * CAP + ps[k]) * HDIM + i];
        }
        out[(long)t * HDIM + i] = v;
    }
}

// ============================================================
extern "C" void kernel_launch(void* const* d_in, const int* in_sizes, int n_in,
                              void* d_out, int out_size)
{
    const float* hidden = (const float*)d_in[0];
    const float* cosb   = (const float*)d_in[1];
    const float* sinb   = (const float*)d_in[2];
    const float* ln1    = (const float*)d_in[3];
    const float* ln2    = (const float*)d_in[4];
    const float* Wqkv   = (const float*)d_in[5];
    const float* Wo     = (const float*)d_in[6];
    const float* qnw    = (const float*)d_in[7];
    const float* knw    = (const float*)d_in[8];
    const float* Wgu    = (const float*)d_in[9];
    const float* Wd     = (const float*)d_in[10];
    const float* Wg     = (const float*)d_in[11];
    const float* Wgue   = (const float*)d_in[12];
    const float* Wde    = (const float*)d_in[13];
    float* out = (float*)d_out;

    void *pv;
    float *p_xln, *p_qkv, *p_q, *p_k, *p_v, *p_sc, *p_attnT, *p_tmp, *p_h1, *p_x2;
    float *p_gu, *p_act, *p_mlp, *p_logits, *p_xe, *p_gue, *p_acte, *p_ye;
    int *p_cnt;
    cudaGetSymbolAddress(&pv, g_xln);    p_xln = (float*)pv;
    cudaGetSymbolAddress(&pv, g_qkv);    p_qkv = (float*)pv;
    cudaGetSymbolAddress(&pv, g_q);      p_q = (float*)pv;
    cudaGetSymbolAddress(&pv, g_k);      p_k = (float*)pv;
    cudaGetSymbolAddress(&pv, g_v);      p_v = (float*)pv;
    cudaGetSymbolAddress(&pv, g_sc);     p_sc = (float*)pv;
    cudaGetSymbolAddress(&pv, g_attnT);  p_attnT = (float*)pv;
    cudaGetSymbolAddress(&pv, g_tmp);    p_tmp = (float*)pv;
    cudaGetSymbolAddress(&pv, g_h1);     p_h1 = (float*)pv;
    cudaGetSymbolAddress(&pv, g_x2);     p_x2 = (float*)pv;
    cudaGetSymbolAddress(&pv, g_gu);     p_gu = (float*)pv;
    cudaGetSymbolAddress(&pv, g_act);    p_act = (float*)pv;
    cudaGetSymbolAddress(&pv, g_mlp);    p_mlp = (float*)pv;
    cudaGetSymbolAddress(&pv, g_logits); p_logits = (float*)pv;
    cudaGetSymbolAddress(&pv, g_xe);     p_xe = (float*)pv;
    cudaGetSymbolAddress(&pv, g_gue);    p_gue = (float*)pv;
    cudaGetSymbolAddress(&pv, g_acte);   p_acte = (float*)pv;
    cudaGetSymbolAddress(&pv, g_ye);     p_ye = (float*)pv;
    cudaGetSymbolAddress(&pv, g_cnt);    p_cnt = (int*)pv;

    zero_cnt_k<<<1, 64>>>();

    // x = rmsnorm(hidden, ln1)
    rmsnorm_k<<<SQ, 256>>>(hidden, ln1, p_xln, HDIM);

    // qkv = x @ Wqkv   (1024 x 2048, K=1024)
    sgemm_t<0><<<dim3(QKVN/64, SQ/64, 1), 256>>>(p_xln, Wqkv, p_qkv,
        SQ, QKVN, HDIM, HDIM, QKVN, QKVN, 1.f, 0, 0, 0, 1, nullptr);

    // rope + qk norm + split
    rope_split_k<<<dim3(SQ, 32), 64>>>(cosb, sinb, qnw, knw);

    // scores[h] = (1/8) q[h] @ k[h/2]^T  (batched NT)
    sgemm_t<1><<<dim3(SQ/64, SQ/64, NHQ), 256>>>(p_q, p_k, p_sc,
        SQ, SQ, HD, HD, HD, SQ, 0.125f,
        (long)SQ*HD, (long)SQ*HD, (long)SQ*SQ, 2, nullptr);

    softmax_causal_k<<<dim3(SQ, NHQ), 256>>>();

    // attnT[:, h*64:(h+1)*64] = P[h] @ v[h/2]
    sgemm_t<0><<<dim3(1, SQ/64, NHQ), 256>>>(p_sc, p_v, p_attnT,
        SQ, HD, SQ, SQ, HD, HDIM, 1.f,
        (long)SQ*SQ, (long)SQ*HD, (long)HD, 2, nullptr);

    // attn proj + residual
    sgemm_t<0><<<dim3(HDIM/64, SQ/64, 1), 256>>>(p_attnT, Wo, p_tmp,
        SQ, HDIM, HDIM, HDIM, HDIM, HDIM, 1.f, 0, 0, 0, 1, nullptr);
    add_k<<<(SQ*HDIM)/256, 256>>>(hidden, p_tmp, p_h1, SQ*HDIM);

    // x2 = rmsnorm(h1, ln2)
    rmsnorm_k<<<SQ, 256>>>(p_h1, ln2, p_x2, HDIM);

    // shared MLP
    sgemm_t<0><<<dim3((2*IS)/64, SQ/64, 1), 256>>>(p_x2, Wgu, p_gu,
        SQ, 2*IS, HDIM, HDIM, 2*IS, 2*IS, 1.f, 0, 0, 0, 1, nullptr);
    swiglu_shared_k<<<SQ, 256>>>();
    sgemm_t<0><<<dim3(HDIM/64, SQ/64, 1), 256>>>(p_act, Wd, p_mlp,
        SQ, HDIM, IS, IS, HDIM, HDIM, 1.f, 0, 0, 0, 1, nullptr);

    // gate logits + routing
    sgemm_t<0><<<dim3(NE/64, SQ/64, 1), 256>>>(p_x2, Wg, p_logits,
        SQ, NE, HDIM, HDIM, NE, NE, 1.f, 0, 0, 0, 1, nullptr);
    route_k<<<SQ/256, 256>>>();
    assign_pos_k<<<NE, 256>>>();
    scatter_xe_k<<<SQ*TOPK, 256>>>();

    // expert GEMM 1: gu_e = xe[e] @ Wgu_experts[e]   (count-limited)
    sgemm_t<0><<<dim3((2*IS)/64, CAP/64, NE), 256>>>(p_xe, Wgue, p_gue,
        CAP, 2*IS, HDIM, HDIM, 2*IS, 2*IS, 1.f,
        (long)CAP*HDIM, (long)HDIM*2*IS, (long)CAP*2*IS, 1, p_cnt);

    swiglu_expert_k<<<NE*CAP, 256>>>();

    // expert GEMM 2: ye = act_e @ Wd_experts[e]
    sgemm_t<0><<<dim3(HDIM/64, CAP/64, NE), 256>>>(p_acte, Wde, p_ye,
        CAP, HDIM, IS, IS, HDIM, HDIM, 1.f,
        (long)CAP*IS, (long)IS*HDIM, (long)CAP*HDIM, 1, p_cnt);

    // final combine: out = h1 + shared + moe
    combine_k<<<SQ, 256>>>(out);
}

// round 5
// speedup vs baseline: 1.4946x; 1.4946x over previous
#include <cuda_runtime.h>
#include <math.h>
#include <stdint.h>

// ---- problem constants ----
#define SQ    1024      // sequence length
#define HDIM  1024      // hidden size
#define NHQ   16        // query heads
#define NKV   8         // kv heads
#define HD    64        // head dim
#define NE    64        // experts
#define TOPK  8
#define CAP   512       // capacity
#define IS    3072      // intermediate
#define QKVN  2048      // (16+2*8)*64

// ---- scratch (device globals; allocation-free) ----
__device__ float g_xln[SQ*HDIM];
__device__ float g_qkv[SQ*QKVN];
__device__ float g_q[NHQ*SQ*HD];
__device__ float g_k[NKV*SQ*HD];
__device__ float g_v[NKV*SQ*HD];
__device__ float g_sc[(size_t)NHQ*SQ*SQ];          // 67 MB
__device__ float g_attnT[SQ*HDIM];
__device__ float g_tmp[SQ*HDIM];
__device__ float g_h1[SQ*HDIM];
__device__ float g_x2[SQ*HDIM];
__device__ float g_gu[SQ*2*IS];
__device__ float g_act[SQ*IS];
__device__ float g_mlp[SQ*HDIM];
__device__ float g_logits[SQ*NE];
__device__ int   g_eidx[SQ*TOPK];
__device__ float g_ew[SQ*TOPK];
__device__ int   g_epos[SQ*TOPK];
__device__ int   g_cnt[NE];
__device__ float g_xe[(size_t)NE*CAP*HDIM];        // 128 MB
__device__ float g_gue[(size_t)NE*CAP*2*IS];       // 805 MB
__device__ float g_acte[(size_t)NE*CAP*IS];        // 402 MB
__device__ float g_ye[(size_t)NE*CAP*HDIM];        // 128 MB

// ============================================================
// fp32 SIMT SGEMM (kept for attention path / routing exactness)
// ============================================================
template<int TB>
__global__ void __launch_bounds__(256) sgemm_t(
    const float* __restrict__ A, const float* __restrict__ B,
    float* __restrict__ C, int M, int N, int K,
    int lda, int ldb, int ldc, float alpha,
    long sA, long sB, long sC, int bdiv, const int* mcnt)
{
    int z = blockIdx.z;
    A += (long)z * sA;
    B += (long)(z / bdiv) * sB;
    C += (long)z * sC;
    int m0 = blockIdx.y * 64;
    int n0 = blockIdx.x * 64;
    if (mcnt) {
        int me = mcnt[z]; if (me > M) me = M;
        if (m0 >= me) return;
    }
    __shared__ float As[16][64];
    __shared__ float Bs[16][64];
    const int tid = threadIdx.x;
    const int tx = tid & 15, ty = tid >> 4;
    const int am = tid >> 2, ak = (tid & 3) << 2;
    const int bn = (tid & 15) << 2, bk = tid >> 4;
    float acc[4][4] = {};
    for (int k0 = 0; k0 < K; k0 += 16) {
        float4 av = *(const float4*)(A + (long)(m0 + am) * lda + (k0 + ak));
        As[ak+0][am] = av.x; As[ak+1][am] = av.y;
        As[ak+2][am] = av.z; As[ak+3][am] = av.w;
        if (TB == 0) {
            float4 bv = *(const float4*)(B + (long)(k0 + bk) * ldb + (n0 + bn));
            *(float4*)(&Bs[bk][bn]) = bv;
        } else {
            float4 bv = *(const float4*)(B + (long)(n0 + am) * ldb + (k0 + ak));
            Bs[ak+0][am] = bv.x; Bs[ak+1][am] = bv.y;
            Bs[ak+2][am] = bv.z; Bs[ak+3][am] = bv.w;
        }
        __syncthreads();
        #pragma unroll
        for (int kk = 0; kk < 16; kk++) {
            float a0 = As[kk][ty*4+0], a1 = As[kk][ty*4+1];
            float a2 = As[kk][ty*4+2], a3 = As[kk][ty*4+3];
            float b0 = Bs[kk][tx*4+0], b1 = Bs[kk][tx*4+1];
            float b2 = Bs[kk][tx*4+2], b3 = Bs[kk][tx*4+3];
            acc[0][0] += a0*b0; acc[0][1] += a0*b1; acc[0][2] += a0*b2; acc[0][3] += a0*b3;
            acc[1][0] += a1*b0; acc[1][1] += a1*b1; acc[1][2] += a1*b2; acc[1][3] += a1*b3;
            acc[2][0] += a2*b0; acc[2][1] += a2*b1; acc[2][2] += a2*b2; acc[2][3] += a2*b3;
            acc[3][0] += a3*b0; acc[3][1] += a3*b1; acc[3][2] += a3*b2; acc[3][3] += a3*b3;
        }
        __syncthreads();
    }
    float* Cp = C + (long)(m0 + ty*4) * ldc + n0 + tx*4;
    #pragma unroll
    for (int i = 0; i < 4; i++) {
        #pragma unroll
        for (int j = 0; j < 4; j++) Cp[j] = alpha * acc[i][j];
        Cp += ldc;
    }
}

// ============================================================
// TF32 tensor-core GEMM (mma.sync.m16n8k8), C = A(MxK) @ B(KxN)
// 128x128 tile, BK=32, 256 threads (8 warps as 4m x 2n, 32x64/warp).
// Register-staged global prefetch, single smem buffer.
// Requires M%128==0, N%128==0, K%32==0.
// ============================================================
__device__ __forceinline__ uint32_t f2tf(float x) {
    uint32_t y;
    asm("cvt.rna.tf32.f32 %0, %1;" : "=r"(y) : "f"(x));
    return y;
}

__global__ void __launch_bounds__(256, 1) gemm_tf32(
    const float* __restrict__ Ag, const float* __restrict__ Bg,
    float* __restrict__ Cg, int M, int N, int K,
    int lda, int ldb, int ldc,
    long sA, long sB, long sC, int bdiv, const int* mcnt)
{
    int z = blockIdx.z;
    const float* A = Ag + (long)z * sA;
    const float* B = Bg + (long)(z / bdiv) * sB;
    float* C = Cg + (long)z * sC;
    int m0 = blockIdx.y * 128;
    int n0 = blockIdx.x * 128;
    if (mcnt) {
        int me = mcnt[z]; if (me > M) me = M;
        if (m0 >= me) return;
    }

    __shared__ float As[32][133];   // [k][m], padded (conflict-free transposed stores)
    __shared__ float Bs[32][132];   // [k][n], padded, float4-aligned rows

    const int tid  = threadIdx.x;
    const int wid  = tid >> 5;
    const int lane = tid & 31;
    const int g    = lane >> 2;     // group id (0..7)
    const int tg   = lane & 3;      // thread-in-group (0..3)
    const int wm   = wid & 3;       // warp m index (0..3)  -> 32 rows
    const int wn   = wid >> 2;      // warp n index (0..1)  -> 64 cols

    // loader mapping
    const int rowA = tid >> 1;           // 0..127
    const int kbA  = (tid & 1) * 16;     // 0 or 16
    const int rowB = tid >> 3;           // 0..31
    const int nbB  = (tid & 7) * 16;     // 0..112

    float acc[2][8][4];
    #pragma unroll
    for (int i = 0; i < 2; i++)
        #pragma unroll
        for (int j = 0; j < 8; j++)
            #pragma unroll
            for (int c = 0; c < 4; c++) acc[i][j][c] = 0.f;

    const int nk = K >> 5;
    float4 ra[4], rb[4];

    // prefetch tile 0
    #pragma unroll
    for (int q = 0; q < 4; q++) {
        ra[q] = *(const float4*)(A + (long)(m0 + rowA) * lda + (kbA + 4*q));
        rb[q] = *(const float4*)(B + (long)(rowB) * ldb + (n0 + nbB + 4*q));
    }

    for (int kt = 0; kt < nk; kt++) {
        // stage regs -> smem (with tf32 rounding)
        #pragma unroll
        for (int q = 0; q < 4; q++) {
            As[kbA + 4*q + 0][rowA] = __uint_as_float(f2tf(ra[q].x));
            As[kbA + 4*q + 1][rowA] = __uint_as_float(f2tf(ra[q].y));
            As[kbA + 4*q + 2][rowA] = __uint_as_float(f2tf(ra[q].z));
            As[kbA + 4*q + 3][rowA] = __uint_as_float(f2tf(ra[q].w));
            float4 bv;
            bv.x = __uint_as_float(f2tf(rb[q].x));
            bv.y = __uint_as_float(f2tf(rb[q].y));
            bv.z = __uint_as_float(f2tf(rb[q].z));
            bv.w = __uint_as_float(f2tf(rb[q].w));
            *(float4*)(&Bs[rowB][nbB + 4*q]) = bv;
        }
        __syncthreads();

        // prefetch next tile while computing
        if (kt + 1 < nk) {
            int kof = (kt + 1) << 5;
            #pragma unroll
            for (int q = 0; q < 4; q++) {
                ra[q] = *(const float4*)(A + (long)(m0 + rowA) * lda + (kof + kbA + 4*q));
                rb[q] = *(const float4*)(B + (long)(kof + rowB) * ldb + (n0 + nbB + 4*q));
            }
        }

        // compute: 4 k-steps of 8
        #pragma unroll
        for (int ks = 0; ks < 4; ks++) {
            const int kk = ks * 8;
            uint32_t af[2][4];
            #pragma unroll
            for (int i = 0; i < 2; i++) {
                int mb = wm*32 + i*16 + g;
                af[i][0] = __float_as_uint(As[kk + tg    ][mb    ]);
                af[i][1] = __float_as_uint(As[kk + tg    ][mb + 8]);
                af[i][2] = __float_as_uint(As[kk + tg + 4][mb    ]);
                af[i][3] = __float_as_uint(As[kk + tg + 4][mb + 8]);
            }
            uint32_t bf[8][2];
            #pragma unroll
            for (int j = 0; j < 8; j++) {
                int nb = wn*64 + j*8 + g;
                bf[j][0] = __float_as_uint(Bs[kk + tg    ][nb]);
                bf[j][1] = __float_as_uint(Bs[kk + tg + 4][nb]);
            }
            #pragma unroll
            for (int i = 0; i < 2; i++)
                #pragma unroll
                for (int j = 0; j < 8; j++) {
                    asm volatile(
                        "mma.sync.aligned.m16n8k8.row.col.f32.tf32.tf32.f32 "
                        "{%0,%1,%2,%3}, {%4,%5,%6,%7}, {%8,%9}, {%0,%1,%2,%3};"
                        : "+f"(acc[i][j][0]), "+f"(acc[i][j][1]),
                          "+f"(acc[i][j][2]), "+f"(acc[i][j][3])
                        : "r"(af[i][0]), "r"(af[i][1]), "r"(af[i][2]), "r"(af[i][3]),
                          "r"(bf[j][0]), "r"(bf[j][1]));
                }
        }
        __syncthreads();
    }

    // epilogue
    #pragma unroll
    for (int i = 0; i < 2; i++) {
        int row = m0 + wm*32 + i*16 + g;
        #pragma unroll
        for (int j = 0; j < 8; j++) {
            int col = n0 + wn*64 + j*8 + tg*2;
            C[(long)row * ldc + col    ] = acc[i][j][0];
            C[(long)row * ldc + col + 1] = acc[i][j][1];
            C[(long)(row + 8) * ldc + col    ] = acc[i][j][2];
            C[(long)(row + 8) * ldc + col + 1] = acc[i][j][3];
        }
    }
}

// ---------- small kernels ----------
__global__ void zero_cnt_k() { if (threadIdx.x < NE) g_cnt[threadIdx.x] = 0; }

__global__ void rmsnorm_k(const float* __restrict__ x, const float* __restrict__ w,
                          float* __restrict__ y, int ncols)
{
    int row = blockIdx.x;
    const float* xr = x + (long)row * ncols;
    float ss = 0.f;
    for (int i = threadIdx.x; i < ncols; i += 256) { float v = xr[i]; ss += v * v; }
    __shared__ float red[256];
    red[threadIdx.x] = ss; __syncthreads();
    for (int s = 128; s > 0; s >>= 1) {
        if (threadIdx.x < s) red[threadIdx.x] += red[threadIdx.x + s];
        __syncthreads();
    }
    float inv = rsqrtf(red[0] / (float)ncols + 1e-6f);
    for (int i = threadIdx.x; i < ncols; i += 256)
        y[(long)row * ncols + i] = w[i] * xr[i] * inv;
}

__global__ void rope_split_k(const float* __restrict__ cosb, const float* __restrict__ sinb,
                             const float* __restrict__ qw, const float* __restrict__ knw)
{
    int s = blockIdx.x;
    int hh = blockIdx.y;
    int d = threadIdx.x;
    if (hh >= 24) {
        int kvh = hh - 24;
        int col = kvh * 256 + 192 + d;
        g_v[((long)kvh * SQ + s) * HD + d] = g_qkv[(long)s * QKVN + col];
        return;
    }
    __shared__ float buf[64];
    __shared__ float red2[2];
    int col; float* dst; const float* w;
    if (hh < 16) {
        int kvh = hh >> 1, slot = hh & 1;
        col = kvh * 256 + slot * 64 + d;
        dst = g_q + ((long)hh * SQ + s) * HD;
        w = qw;
    } else {
        int kvh = hh - 16;
        col = kvh * 256 + 128 + d;
        dst = g_k + ((long)kvh * SQ + s) * HD;
        w = knw;
    }
    float v = g_qkv[(long)s * QKVN + col];
    buf[d] = v;
    __syncthreads();
    float rh = (d < 32) ? -buf[d + 32] : buf[d - 32];
    float r = v * cosb[s * HD + d] + rh * sinb[s * HD + d];
    float ss = r * r;
    for (int off = 16; off > 0; off >>= 1) ss += __shfl_xor_sync(0xffffffffu, ss, off);
    if ((d & 31) == 0) red2[d >> 5] = ss;
    __syncthreads();
    float tot = red2[0] + red2[1];
    dst[d] = w[d] * r * rsqrtf(tot / 64.f + 1e-6f);
}

__global__ void softmax_causal_k()
{
    int q = blockIdx.x, h = blockIdx.y, t = threadIdx.x;
    float* row = g_sc + ((size_t)h * SQ + q) * SQ;
    __shared__ float red[256];
    float m = -1e30f;
    for (int k = t; k <= q; k += 256) m = fmaxf(m, row[k]);
    red[t] = m; __syncthreads();
    for (int s = 128; s > 0; s >>= 1) { if (t < s) red[t] = fmaxf(red[t], red[t + s]); __syncthreads(); }
    m = red[0]; __syncthreads();
    float ssum = 0.f;
    for (int k = t; k <= q; k += 256) { float e = expf(row[k] - m); row[k] = e; ssum += e; }
    red[t] = ssum; __syncthreads();
    for (int s = 128; s > 0; s >>= 1) { if (t < s) red[t] += red[t + s]; __syncthreads(); }
    float inv = 1.f / red[0];
    for (int k = t; k <= q; k += 256) row[k] *= inv;
    for (int k = q + 1 + t; k < SQ; k += 256) row[k] = 0.f;
}

__global__ void add_k(const float* __restrict__ a, const float* __restrict__ b,
                      float* __restrict__ c, int n)
{
    int i = blockIdx.x * 256 + threadIdx.x;
    if (i < n) c[i] = a[i] + b[i];
}

__global__ void swiglu_shared_k()
{
    long t = blockIdx.x;
    const float* g = g_gu + t * (2 * IS);
    float* a = g_act + t * IS;
    for (int i = threadIdx.x; i < IS; i += 256) {
        float x1 = g[i], xb = g[IS + i];
        a[i] = x1 * (xb / (1.f + expf(-xb)));
    }
}

__global__ void route_k()
{
    int t = blockIdx.x * 256 + threadIdx.x;
    if (t >= SQ) return;
    float l[NE];
    float m = -1e30f;
    for (int e = 0; e < NE; e++) { l[e] = g_logits[t * NE + e]; m = fmaxf(m, l[e]); }
    float sum = 0.f;
    for (int e = 0; e < NE; e++) { l[e] = expf(l[e] - m); sum += l[e]; }
    float inv = 1.f / sum;
    for (int e = 0; e < NE; e++) l[e] *= inv;
    int chosen[TOPK]; float wv[TOPK]; float wsum = 0.f;
    for (int k = 0; k < TOPK; k++) {
        float best = -1.f; int bi = 0;
        for (int e = 0; e < NE; e++) if (l[e] > best) { best = l[e]; bi = e; }
        chosen[k] = bi; wv[k] = best; l[bi] = -2.f; wsum += best;
    }
    float dn = fmaxf(wsum, 1.1920929e-07f);
    for (int k = 0; k < TOPK; k++) {
        g_eidx[t * TOPK + k] = chosen[k];
        g_ew[t * TOPK + k] = wv[k] / dn;
    }
}

__global__ void assign_pos_k()
{
    int e = blockIdx.x;
    int t = threadIdx.x;
    const int CH = (SQ * TOPK) / 256;
    __shared__ int sc[256];
    __shared__ int off[256];
    int c = 0;
    int base = t * CH;
    for (int i = 0; i < CH; i++) c += (g_eidx[base + i] == e);
    sc[t] = c; __syncthreads();
    if (t == 0) {
        int r = 0;
        for (int i = 0; i < 256; i++) { off[i] = r; r += sc[i]; }
        g_cnt[e] = r;
    }
    __syncthreads();
    int p = off[t];
    for (int i = 0; i < CH; i++) {
        int s = base + i;
        if (g_eidx[s] == e) g_epos[s] = p++;
    }
}

__global__ void scatter_xe_k()
{
    int slot = blockIdx.x;
    int p = g_epos[slot];
    if (p >= CAP) return;
    int e = g_eidx[slot];
    int t = slot >> 3;
    const float* src = g_x2 + (long)t * HDIM;
    float* dst = g_xe + ((size_t)e * CAP + p) * HDIM;
    for (int i = threadIdx.x; i < HDIM; i += 256) dst[i] = src[i];
}

__global__ void swiglu_expert_k()
{
    int row = blockIdx.x;
    int e = row >> 9, r = row & 511;
    int me = g_cnt[e]; if (me > CAP) me = CAP;
    if (r >= me) return;
    const float* g = g_gue + (size_t)row * (2 * IS);
    float* a = g_acte + (size_t)row * IS;
    for (int i = threadIdx.x; i < IS; i += 256) {
        float x1 = g[i], xb = g[IS + i];
        a[i] = x1 * (xb / (1.f + expf(-xb)));
    }
}

__global__ void combine_k(float* __restrict__ out)
{
    int t = blockIdx.x;
    __shared__ int es[TOPK]; __shared__ int ps[TOPK]; __shared__ float ws[TOPK];
    if (threadIdx.x < TOPK) {
        es[threadIdx.x] = g_eidx[t * TOPK + threadIdx.x];
        ps[threadIdx.x] = g_epos[t * TOPK + threadIdx.x];
        ws[threadIdx.x] = g_ew[t * TOPK + threadIdx.x];
    }
    __syncthreads();
    for (int i = threadIdx.x; i < HDIM; i += 256) {
        float v = g_h1[(long)t * HDIM + i] + g_mlp[(long)t * HDIM + i];
        #pragma unroll
        for (int k = 0; k < TOPK; k++) {
            if (ps[k] < CAP)
                v += ws[k] * g_ye[((size_t)es[k] * CAP + ps[k]) * HDIM + i];
        }
        out[(long)t * HDIM + i] = v;
    }
}

// ============================================================
extern "C" void kernel_launch(void* const* d_in, const int* in_sizes, int n_in,
                              void* d_out, int out_size)
{
    const float* hidden = (const float*)d_in[0];
    const float* cosb   = (const float*)d_in[1];
    const float* sinb   = (const float*)d_in[2];
    const float* ln1    = (const float*)d_in[3];
    const float* ln2    = (const float*)d_in[4];
    const float* Wqkv   = (const float*)d_in[5];
    const float* Wo     = (const float*)d_in[6];
    const float* qnw    = (const float*)d_in[7];
    const float* knw    = (const float*)d_in[8];
    const float* Wgu    = (const float*)d_in[9];
    const float* Wd     = (const float*)d_in[10];
    const float* Wg     = (const float*)d_in[11];
    const float* Wgue   = (const float*)d_in[12];
    const float* Wde    = (const float*)d_in[13];
    float* out = (float*)d_out;

    void *pv;
    float *p_xln, *p_qkv, *p_q, *p_k, *p_v, *p_sc, *p_attnT, *p_tmp, *p_h1, *p_x2;
    float *p_gu, *p_act, *p_mlp, *p_logits, *p_xe, *p_gue, *p_acte, *p_ye;
    int *p_cnt;
    cudaGetSymbolAddress(&pv, g_xln);    p_xln = (float*)pv;
    cudaGetSymbolAddress(&pv, g_qkv);    p_qkv = (float*)pv;
    cudaGetSymbolAddress(&pv, g_q);      p_q = (float*)pv;
    cudaGetSymbolAddress(&pv, g_k);      p_k = (float*)pv;
    cudaGetSymbolAddress(&pv, g_v);      p_v = (float*)pv;
    cudaGetSymbolAddress(&pv, g_sc);     p_sc = (float*)pv;
    cudaGetSymbolAddress(&pv, g_attnT);  p_attnT = (float*)pv;
    cudaGetSymbolAddress(&pv, g_tmp);    p_tmp = (float*)pv;
    cudaGetSymbolAddress(&pv, g_h1);     p_h1 = (float*)pv;
    cudaGetSymbolAddress(&pv, g_x2);     p_x2 = (float*)pv;
    cudaGetSymbolAddress(&pv, g_gu);     p_gu = (float*)pv;
    cudaGetSymbolAddress(&pv, g_act);    p_act = (float*)pv;
    cudaGetSymbolAddress(&pv, g_mlp);    p_mlp = (float*)pv;
    cudaGetSymbolAddress(&pv, g_logits); p_logits = (float*)pv;
    cudaGetSymbolAddress(&pv, g_xe);     p_xe = (float*)pv;
    cudaGetSymbolAddress(&pv, g_gue);    p_gue = (float*)pv;
    cudaGetSymbolAddress(&pv, g_acte);   p_acte = (float*)pv;
    cudaGetSymbolAddress(&pv, g_ye);     p_ye = (float*)pv;
    cudaGetSymbolAddress(&pv, g_cnt);    p_cnt = (int*)pv;

    zero_cnt_k<<<1, 64>>>();

    // x = rmsnorm(hidden, ln1)
    rmsnorm_k<<<SQ, 256>>>(hidden, ln1, p_xln, HDIM);

    // qkv = x @ Wqkv  (fp32 — feeds routing chain, keep exact)
    sgemm_t<0><<<dim3(QKVN/64, SQ/64, 1), 256>>>(p_xln, Wqkv, p_qkv,
        SQ, QKVN, HDIM, HDIM, QKVN, QKVN, 1.f, 0, 0, 0, 1, nullptr);

    rope_split_k<<<dim3(SQ, 32), 64>>>(cosb, sinb, qnw, knw);

    // scores (fp32)
    sgemm_t<1><<<dim3(SQ/64, SQ/64, NHQ), 256>>>(p_q, p_k, p_sc,
        SQ, SQ, HD, HD, HD, SQ, 0.125f,
        (long)SQ*HD, (long)SQ*HD, (long)SQ*SQ, 2, nullptr);

    softmax_causal_k<<<dim3(SQ, NHQ), 256>>>();

    // attn @ V (fp32)
    sgemm_t<0><<<dim3(1, SQ/64, NHQ), 256>>>(p_sc, p_v, p_attnT,
        SQ, HD, SQ, SQ, HD, HDIM, 1.f,
        (long)SQ*SQ, (long)SQ*HD, (long)HD, 2, nullptr);

    // Wo + residual (fp32)
    sgemm_t<0><<<dim3(HDIM/64, SQ/64, 1), 256>>>(p_attnT, Wo, p_tmp,
        SQ, HDIM, HDIM, HDIM, HDIM, HDIM, 1.f, 0, 0, 0, 1, nullptr);
    add_k<<<(SQ*HDIM)/256, 256>>>(hidden, p_tmp, p_h1, SQ*HDIM);

    rmsnorm_k<<<SQ, 256>>>(p_h1, ln2, p_x2, HDIM);

    // gate logits + routing FIRST (fp32-exact; independent of MLP results)
    sgemm_t<0><<<dim3(NE/64, SQ/64, 1), 256>>>(p_x2, Wg, p_logits,
        SQ, NE, HDIM, HDIM, NE, NE, 1.f, 0, 0, 0, 1, nullptr);
    route_k<<<SQ/256, 256>>>();
    assign_pos_k<<<NE, 256>>>();
    scatter_xe_k<<<SQ*TOPK, 256>>>();

    // shared MLP (tf32 tensor cores)
    gemm_tf32<<<dim3((2*IS)/128, SQ/128, 1), 256>>>(p_x2, Wgu, p_gu,
        SQ, 2*IS, HDIM, HDIM, 2*IS, 2*IS, 0, 0, 0, 1, nullptr);
    swiglu_shared_k<<<SQ, 256>>>();
    gemm_tf32<<<dim3(HDIM/128, SQ/128, 1), 256>>>(p_act, Wd, p_mlp,
        SQ, HDIM, IS, IS, HDIM, HDIM, 0, 0, 0, 1, nullptr);

    // expert GEMM 1 (tf32, count-limited): gu_e = xe[e] @ Wgu_experts[e]
    gemm_tf32<<<dim3((2*IS)/128, CAP/128, NE), 256>>>(p_xe, Wgue, p_gue,
        CAP, 2*IS, HDIM, HDIM, 2*IS, 2*IS,
        (long)CAP*HDIM, (long)HDIM*2*IS, (long)CAP*2*IS, 1, p_cnt);

    swiglu_expert_k<<<NE*CAP, 256>>>();

    // expert GEMM 2 (tf32): ye = act_e @ Wd_experts[e]
    gemm_tf32<<<dim3(HDIM/128, CAP/128, NE), 256>>>(p_acte, Wde, p_ye,
        CAP, HDIM, IS, IS, HDIM, HDIM,
        (long)CAP*IS, (long)IS*HDIM, (long)CAP*HDIM, 1, p_cnt);

    combine_k<<<SQ, 256>>>(out);
}